// round 2
// baseline (speedup 1.0000x reference)
#include <cuda_runtime.h>
#include <math.h>

// ---------------------------------------------------------------------------
// SelectiveModel: B=32768, T=23 steps, H=64, SLOTS=8, VOCAB=64.
//
// Structural collapse (unchanged from R1):
//  - gating MLP  -> S[64][64] sigmoid table; recurrence is integer state.
//  - readout L1  -> QP[67]/MP[64] tables; pre1 = QP[qt] + 0.125 * sum MP[mt_s]
//  - only the 64x64 L2 GEMV remains as FP work.
//
// R2 changes: 4 threads/batch (4096 warps), fused L1->L2 with packed
// fma.rn.f32x2, coalesced direct stores, 3 blocks/SM occupancy.
// ---------------------------------------------------------------------------

__device__ float g_S [64 * 64];   // sigmoid score table
__device__ float g_QP[66 * 68];   // query part of layer-1 (+rb1), padded rows
__device__ float g_MP[64 * 68];   // memory part of layer-1, padded rows

// ---------------- packed fp32x2 helpers (Blackwell FFMA2) -------------------
__device__ __forceinline__ unsigned long long pk2(float lo, float hi) {
    unsigned long long r;
    asm("mov.b64 %0, {%1, %2};" : "=l"(r) : "f"(lo), "f"(hi));
    return r;
}
__device__ __forceinline__ void upk2(unsigned long long v, float& lo, float& hi) {
    asm("mov.b64 {%0, %1}, %2;" : "=f"(lo), "=f"(hi) : "l"(v));
}
__device__ __forceinline__ void fma2(unsigned long long& d,
                                     unsigned long long a, unsigned long long b) {
    asm("fma.rn.f32x2 %0, %1, %2, %0;" : "+l"(d) : "l"(a), "l"(b));
}

// ============================ K1: table precompute ==========================
// grid = 129 blocks x 128 threads (unchanged from R1 — measured ~1.6us total)
__global__ void __launch_bounds__(128) precompute_kernel(
    const float* __restrict__ embed, const float* __restrict__ gw1,
    const float* __restrict__ gb1,   const float* __restrict__ gw2,
    const float* __restrict__ gb2,   const float* __restrict__ rw1,
    const float* __restrict__ rb1)
{
    const int bid = blockIdx.x, tid = threadIdx.x;
    if (bid < 64) {
        __shared__ float sEmb [64 * 65];
        __shared__ float sGw1 [128 * 32];
        __shared__ float sEdot[32];
        __shared__ float sMdot[64 * 33];
        for (int i = tid; i < 64 * 64; i += 128)
            sEmb[(i >> 6) * 65 + (i & 63)] = embed[i];
        for (int i = tid; i < 128 * 32; i += 128) sGw1[i] = gw1[i];
        __syncthreads();
        const int c = bid;
        if (tid < 32) {
            float acc = 0.f;
            #pragma unroll 16
            for (int k = 0; k < 64; k++) acc += sEmb[c * 65 + k] * sGw1[k * 32 + tid];
            sEdot[tid] = acc;
        }
        {
            const int m = tid & 63, half = tid >> 6;
            float acc[16];
            #pragma unroll
            for (int jj = 0; jj < 16; jj++) acc[jj] = 0.f;
            for (int k = 0; k < 64; k++) {
                const float e = sEmb[m * 65 + k];
                #pragma unroll
                for (int jj = 0; jj < 16; jj++)
                    acc[jj] += e * sGw1[(64 + k) * 32 + half * 16 + jj];
            }
            #pragma unroll
            for (int jj = 0; jj < 16; jj++) sMdot[m * 33 + half * 16 + jj] = acc[jj];
        }
        __syncthreads();
        if (tid < 64) {
            float acc = gb2[0];
            #pragma unroll
            for (int j = 0; j < 32; j++) {
                const float hv = sEdot[j] + sMdot[tid * 33 + j] + gb1[j];
                acc += fmaxf(hv, 0.f) * gw2[j];
            }
            g_S[c * 64 + tid] = 1.f / (1.f + expf(-acc));
        }
    } else if (bid < 97) {
        const int r = (bid - 64) * 2 + (tid >> 6);
        const int j = tid & 63;
        if (r < 66) {
            float acc = rb1[j];
            #pragma unroll 16
            for (int k = 0; k < 64; k++) acc += embed[r * 64 + k] * rw1[k * 64 + j];
            g_QP[r * 68 + j] = acc;
            if (j < 4) g_QP[r * 68 + 64 + j] = 0.f;
        }
    } else {
        const int r = (bid - 97) * 2 + (tid >> 6);
        const int j = tid & 63;
        float acc = 0.f;
        #pragma unroll 16
        for (int k = 0; k < 64; k++) acc += embed[r * 64 + k] * rw1[(64 + k) * 64 + j];
        g_MP[r * 68 + j] = acc;
        if (j < 4) g_MP[r * 68 + 64 + j] = 0.f;
    }
}

// ============================== K2: main ====================================
// 256 threads/block, 4 threads per batch -> 64 batches/block, grid = 512.
// thread lane4 = tid&3 owns output logits v = lane4*4 + i*16 + k (i,k in 0..3)
// smem (floats): sS 64*65 | sQP 66*68 | sMP 64*68 | sRW2 64*64 | sRB2 64 | tok
#define SS_F   (64 * 65)
#define SQP_F  (66 * 68)
#define SMP_F  (64 * 68)
#define SRW2_F (64 * 64)
#define SRB2_F 64
#define K2_SMEM_BYTES ((SS_F + SQP_F + SMP_F + SRW2_F + SRB2_F) * 4 + 64 * 24)

__global__ void __launch_bounds__(256, 3) main_kernel(
    const int* __restrict__ seqs32, const int* __restrict__ qtok32,
    const float* __restrict__ rw2,  const float* __restrict__ rb2,
    float* __restrict__ out)
{
    extern __shared__ float smem[];
    float* sS   = smem;                         // padded rows of 65
    float* sQP  = sS   + SS_F;
    float* sMP  = sQP  + SQP_F;
    float* sRW2 = sMP  + SMP_F;
    float* sRB2 = sRW2 + SRW2_F;
    unsigned char* sTok = (unsigned char*)(sRB2 + SRB2_F);
    const int tid = threadIdx.x, bid = blockIdx.x;

    // int64 vs int32 token dtype detection (odd LE words of small int64 == 0)
    const int oddOr = seqs32[1] | seqs32[3] | seqs32[5] | seqs32[7] |
                      seqs32[9] | seqs32[11] | seqs32[13] | seqs32[15];
    const bool is64 = (oddOr == 0);

    // ---- tables -> shared ----
    for (int i = tid; i < 4096; i += 256)
        sS[(i >> 6) * 65 + (i & 63)] = g_S[i];
    {
        const float4* g; float4* s;
        g = (const float4*)g_QP; s = (float4*)sQP;  for (int i = tid; i < 1122; i += 256) s[i] = g[i];
        g = (const float4*)g_MP; s = (float4*)sMP;  for (int i = tid; i < 1088; i += 256) s[i] = g[i];
        g = (const float4*)rw2;  s = (float4*)sRW2; for (int i = tid; i < 1024; i += 256) s[i] = g[i];
        g = (const float4*)rb2;  s = (float4*)sRB2; for (int i = tid; i < 16;   i += 256) s[i] = g[i];
    }
    // ---- stage 64 seq rows as token bytes ----
    {
        const int base = bid * 64 * 24;
        for (int i = tid; i < 64 * 24; i += 256) {
            const int v = is64 ? seqs32[2 * (base + i)] : seqs32[base + i];
            sTok[i] = (unsigned char)v;
        }
    }
    const int lane4 = tid & 3;          // output-column group
    const int bl    = tid >> 2;         // local batch 0..63
    const int b     = bid * 64 + bl;
    const int qt    = is64 ? qtok32[2 * b] : qtok32[b];
    __syncthreads();

    // ---- recurrence (integer slot state + S-table argmax) ----
    const unsigned char* myTok = sTok + bl * 24;
    int moff[8];                         // mt[s] * 68 (MP row offsets)
    {
        int mt[8];
        #pragma unroll
        for (int s = 0; s < 8; s++) mt[s] = myTok[s];
        #pragma unroll
        for (int t = 8; t < 23; t++) {
            const int c = myTok[t];
            const float* Srow = sS + c * 65;
            float best = Srow[mt[0]];
            int bi = 0;
            #pragma unroll
            for (int s = 1; s < 8; s++) {
                const float sc = Srow[mt[s]];
                if (sc > best) { best = sc; bi = s; }   // strict > == first-max
            }
            #pragma unroll
            for (int s = 0; s < 8; s++) if (bi == s) mt[s] = c;
        }
        #pragma unroll
        for (int s = 0; s < 8; s++) moff[s] = mt[s] * 68;
    }

    // ---- fused L1 (h) -> L2 (GEMV), packed f32x2 ----
    unsigned long long acc[8];           // 16 output logits as 8 fp32x2 pairs
    {
        const float* rb = sRB2 + (lane4 << 2);
        #pragma unroll
        for (int i = 0; i < 4; i++) {
            const ulonglong2 r = *(const ulonglong2*)(rb + (i << 4));
            acc[2 * i] = r.x; acc[2 * i + 1] = r.y;
        }
    }
    const unsigned long long E2 = pk2(0.125f, 0.125f);
    const float* qpRow = sQP + qt * 68;
    #pragma unroll 2
    for (int g = 0; g < 16; g++) {       // j = 4g .. 4g+3
        const ulonglong2 q4 = *(const ulonglong2*)(qpRow + (g << 2));
        unsigned long long h01 = q4.x, h23 = q4.y;
        #pragma unroll
        for (int s = 0; s < 8; s++) {
            const ulonglong2 m4 = *(const ulonglong2*)(sMP + moff[s] + (g << 2));
            fma2(h01, m4.x, E2);
            fma2(h23, m4.y, E2);
        }
        float h0, h1, h2, h3;
        upk2(h01, h0, h1); upk2(h23, h2, h3);
        h0 = fmaxf(h0, 0.f); h1 = fmaxf(h1, 0.f);
        h2 = fmaxf(h2, 0.f); h3 = fmaxf(h3, 0.f);
        unsigned long long hh[4] = { pk2(h0, h0), pk2(h1, h1),
                                     pk2(h2, h2), pk2(h3, h3) };
        #pragma unroll
        for (int jj = 0; jj < 4; jj++) {
            const float* wr = sRW2 + (((g << 2) + jj) << 6) + (lane4 << 2);
            #pragma unroll
            for (int i = 0; i < 4; i++) {
                const ulonglong2 w = *(const ulonglong2*)(wr + (i << 4));
                fma2(acc[2 * i],     hh[jj], w.x);
                fma2(acc[2 * i + 1], hh[jj], w.y);
            }
        }
    }

    // ---- coalesced direct stores (each warp: 8 full 64B segments / STG) ----
    float* op = out + (b << 6) + (lane4 << 2);
    #pragma unroll
    for (int i = 0; i < 4; i++) {
        float4 v;
        upk2(acc[2 * i],     v.x, v.y);
        upk2(acc[2 * i + 1], v.z, v.w);
        *(float4*)(op + (i << 4)) = v;
    }
}

// ============================== launch ======================================
extern "C" void kernel_launch(void* const* d_in, const int* in_sizes, int n_in,
                              void* d_out, int out_size)
{
    const int*   seqs  = (const int*)  d_in[0];
    const int*   qtok  = (const int*)  d_in[1];
    const float* embed = (const float*)d_in[2];
    const float* gw1   = (const float*)d_in[3];
    const float* gb1   = (const float*)d_in[4];
    const float* gw2   = (const float*)d_in[5];
    const float* gb2   = (const float*)d_in[6];
    const float* rw1   = (const float*)d_in[7];
    const float* rb1   = (const float*)d_in[8];
    const float* rw2   = (const float*)d_in[9];
    const float* rb2   = (const float*)d_in[10];

    cudaFuncSetAttribute(main_kernel,
                         cudaFuncAttributeMaxDynamicSharedMemorySize,
                         K2_SMEM_BYTES);

    precompute_kernel<<<129, 128>>>(embed, gw1, gb1, gw2, gb2, rw1, rb1);
    main_kernel<<<512, 256, K2_SMEM_BYTES>>>(seqs, qtok, rw2, rb2, (float*)d_out);
}

// round 3
// speedup vs baseline: 1.2264x; 1.2264x over previous
#include <cuda_runtime.h>
#include <math.h>

// ---------------------------------------------------------------------------
// SelectiveModel: B=32768, T=23, H=64, SLOTS=8, VOCAB=64.
//
// Structural collapse (R1): gating MLP -> S[64][64] sigmoid table, recurrence
// is pure integer state; readout L1 -> QP/MP tables; only the 64x64 L2 GEMV
// remains as FP work.
//
// R3: two-phase main kernel, 2 threads/batch.
//   Phase 1: thread (bl, half) computes recurrence (dup on lane pairs, free in
//            SIMT) and its j-half of h; writes h transposed HT[j][bl].
//   Phase 2: warp-cooperative GEMM, warp tile 16 batches x 64 cols, thread
//            tile 4 batches x 8 cols; rw2 row loaded once per warp per k.
//   All FP math in packed fma.rn.f32x2.
// ---------------------------------------------------------------------------

__device__ float g_S [64 * 64];   // sigmoid score table
__device__ float g_QP[66 * 68];   // query part of layer-1 (+rb1), padded rows
__device__ float g_MP[64 * 68];   // memory part of layer-1, padded rows

// ---------------- packed fp32x2 helpers -------------------------------------
__device__ __forceinline__ unsigned long long pk2(float lo, float hi) {
    unsigned long long r;
    asm("mov.b64 %0, {%1, %2};" : "=l"(r) : "f"(lo), "f"(hi));
    return r;
}
__device__ __forceinline__ void upk2(unsigned long long v, float& lo, float& hi) {
    asm("mov.b64 {%0, %1}, %2;" : "=f"(lo), "=f"(hi) : "l"(v));
}
__device__ __forceinline__ void fma2(unsigned long long& d,
                                     unsigned long long a, unsigned long long b) {
    asm("fma.rn.f32x2 %0, %1, %2, %0;" : "+l"(d) : "l"(a), "l"(b));
}

// ============================ K1: table precompute ==========================
__global__ void __launch_bounds__(128) precompute_kernel(
    const float* __restrict__ embed, const float* __restrict__ gw1,
    const float* __restrict__ gb1,   const float* __restrict__ gw2,
    const float* __restrict__ gb2,   const float* __restrict__ rw1,
    const float* __restrict__ rb1)
{
    const int bid = blockIdx.x, tid = threadIdx.x;
    if (bid < 64) {
        __shared__ float sEmb [64 * 65];
        __shared__ float sGw1 [128 * 32];
        __shared__ float sEdot[32];
        __shared__ float sMdot[64 * 33];
        for (int i = tid; i < 64 * 64; i += 128)
            sEmb[(i >> 6) * 65 + (i & 63)] = embed[i];
        for (int i = tid; i < 128 * 32; i += 128) sGw1[i] = gw1[i];
        __syncthreads();
        const int c = bid;
        if (tid < 32) {
            float acc = 0.f;
            #pragma unroll 16
            for (int k = 0; k < 64; k++) acc += sEmb[c * 65 + k] * sGw1[k * 32 + tid];
            sEdot[tid] = acc;
        }
        {
            const int m = tid & 63, half = tid >> 6;
            float acc[16];
            #pragma unroll
            for (int jj = 0; jj < 16; jj++) acc[jj] = 0.f;
            for (int k = 0; k < 64; k++) {
                const float e = sEmb[m * 65 + k];
                #pragma unroll
                for (int jj = 0; jj < 16; jj++)
                    acc[jj] += e * sGw1[(64 + k) * 32 + half * 16 + jj];
            }
            #pragma unroll
            for (int jj = 0; jj < 16; jj++) sMdot[m * 33 + half * 16 + jj] = acc[jj];
        }
        __syncthreads();
        if (tid < 64) {
            float acc = gb2[0];
            #pragma unroll
            for (int j = 0; j < 32; j++) {
                const float hv = sEdot[j] + sMdot[tid * 33 + j] + gb1[j];
                acc += fmaxf(hv, 0.f) * gw2[j];
            }
            g_S[c * 64 + tid] = 1.f / (1.f + expf(-acc));
        }
    } else if (bid < 97) {
        const int r = (bid - 64) * 2 + (tid >> 6);
        const int j = tid & 63;
        if (r < 66) {
            float acc = rb1[j];
            #pragma unroll 16
            for (int k = 0; k < 64; k++) acc += embed[r * 64 + k] * rw1[k * 64 + j];
            g_QP[r * 68 + j] = acc;
            if (j < 4) g_QP[r * 68 + 64 + j] = 0.f;
        }
    } else {
        const int r = (bid - 97) * 2 + (tid >> 6);
        const int j = tid & 63;
        float acc = 0.f;
        #pragma unroll 16
        for (int k = 0; k < 64; k++) acc += embed[r * 64 + k] * rw1[(64 + k) * 64 + j];
        g_MP[r * 68 + j] = acc;
        if (j < 4) g_MP[r * 68 + 64 + j] = 0.f;
    }
}

// ============================== K2: main ====================================
// grid = 256 blocks x 256 threads; block owns 128 batches (2 threads/batch).
#define SS_F   (64 * 65)     // 4160
#define SQP_F  (66 * 68)     // 4488
#define SMP_F  (64 * 68)     // 4352
#define SRW2_F (64 * 68)     // 4352 (rows padded to 68)
#define SRB2_F 64
#define SHT_F  (64 * 132)    // 8448, HT[j][bl], stride 132
#define K2_SMEM_BYTES ((SS_F + SQP_F + SMP_F + SRW2_F + SRB2_F + SHT_F) * 4 + 128 * 24)

__global__ void __launch_bounds__(256, 2) main_kernel(
    const int* __restrict__ seqs32, const int* __restrict__ qtok32,
    const float* __restrict__ rw2,  const float* __restrict__ rb2,
    float* __restrict__ out)
{
    extern __shared__ float smem[];
    float* sS   = smem;                    // padded rows of 65
    float* sQP  = sS   + SS_F;
    float* sMP  = sQP  + SQP_F;
    float* sRW2 = sMP  + SMP_F;
    float* sRB2 = sRW2 + SRW2_F;
    float* sHT  = sRB2 + SRB2_F;
    unsigned char* sTok = (unsigned char*)(sHT + SHT_F);
    const int tid = threadIdx.x, bid = blockIdx.x;

    // int64 vs int32 token dtype detection (odd LE words of small int64 == 0)
    const int oddOr = seqs32[1] | seqs32[3] | seqs32[5] | seqs32[7] |
                      seqs32[9] | seqs32[11] | seqs32[13] | seqs32[15];
    const bool is64 = (oddOr == 0);

    // ---- tables -> shared ----
    for (int i = tid; i < 4096; i += 256)
        sS[(i >> 6) * 65 + (i & 63)] = g_S[i];
    {
        const float4* g; float4* s;
        g = (const float4*)g_QP; s = (float4*)sQP;  for (int i = tid; i < 1122; i += 256) s[i] = g[i];
        g = (const float4*)g_MP; s = (float4*)sMP;  for (int i = tid; i < 1088; i += 256) s[i] = g[i];
        g = (const float4*)rb2;  s = (float4*)sRB2; for (int i = tid; i < 16;   i += 256) s[i] = g[i];
        // rw2 rows re-padded 64 -> 68 floats
        g = (const float4*)rw2;  s = (float4*)sRW2;
        for (int i = tid; i < 1024; i += 256) s[(i >> 4) * 17 + (i & 15)] = g[i];
    }
    // ---- stage 128 seq rows as token bytes ----
    {
        const int base = bid * 128 * 24;
        for (int i = tid; i < 128 * 24; i += 256) {
            const int v = is64 ? seqs32[2 * (base + i)] : seqs32[base + i];
            sTok[i] = (unsigned char)v;
        }
    }
    const int bl   = tid >> 1;          // local batch 0..127
    const int half = tid & 1;           // j-half owner
    const int gb   = bid * 128 + bl;
    const int qt   = is64 ? qtok32[2 * gb] : qtok32[gb];
    __syncthreads();

    // ============ Phase 1: recurrence + this thread's j-half of h ===========
    {
        const unsigned char* myTok = sTok + bl * 24;
        int moff[8];
        {
            int mt[8];
            #pragma unroll
            for (int s = 0; s < 8; s++) mt[s] = myTok[s];
            #pragma unroll
            for (int t = 8; t < 23; t++) {
                const int c = myTok[t];
                const float* Srow = sS + c * 65;
                float best = Srow[mt[0]];
                int bi = 0;
                #pragma unroll
                for (int s = 1; s < 8; s++) {
                    const float sc = Srow[mt[s]];
                    if (sc > best) { best = sc; bi = s; }  // strict > == first-max
                }
                #pragma unroll
                for (int s = 0; s < 8; s++) if (bi == s) mt[s] = c;
            }
            #pragma unroll
            for (int s = 0; s < 8; s++) moff[s] = mt[s] * 68 + half * 32;
        }

        const unsigned long long E2 = pk2(0.125f, 0.125f);
        const float* qp = sQP + qt * 68 + half * 32;
        float* htCol = sHT + (half * 32) * 132 + bl;
        #pragma unroll
        for (int g = 0; g < 8; g++) {          // j = half*32 + 4g .. +3
            const ulonglong2 q4 = *(const ulonglong2*)(qp + (g << 2));
            unsigned long long h01 = q4.x, h23 = q4.y;
            #pragma unroll
            for (int s = 0; s < 8; s++) {
                const ulonglong2 m4 = *(const ulonglong2*)(sMP + moff[s] + (g << 2));
                fma2(h01, m4.x, E2);
                fma2(h23, m4.y, E2);
            }
            float h0, h1, h2, h3;
            upk2(h01, h0, h1); upk2(h23, h2, h3);
            htCol[(4 * g + 0) * 132] = fmaxf(h0, 0.f);
            htCol[(4 * g + 1) * 132] = fmaxf(h1, 0.f);
            htCol[(4 * g + 2) * 132] = fmaxf(h2, 0.f);
            htCol[(4 * g + 3) * 132] = fmaxf(h3, 0.f);
        }
    }
    __syncthreads();

    // ============ Phase 2: warp-cooperative L2 GEMM ==========================
    // warp w: batches w*16..w*16+15; lane: bg=lane>>3 (4 batches), cg=lane&7
    // (8 cols). Thread computes 4 batches x 8 cols.
    const int w = tid >> 5, lane = tid & 31;
    const int bg = lane >> 3, cg = lane & 7;
    const float* hcol = sHT + w * 16 + bg * 4;     // + k*132
    const float* wrow = sRW2 + cg * 8;             // + k*68

    unsigned long long acc[16];                    // [batch][colpair]
    {
        const ulonglong2 r0 = *(const ulonglong2*)(sRB2 + cg * 8);
        const ulonglong2 r1 = *(const ulonglong2*)(sRB2 + cg * 8 + 4);
        #pragma unroll
        for (int b = 0; b < 4; b++) {
            acc[b * 4 + 0] = r0.x; acc[b * 4 + 1] = r0.y;
            acc[b * 4 + 2] = r1.x; acc[b * 4 + 3] = r1.y;
        }
    }
    #pragma unroll 4
    for (int k = 0; k < 64; k++) {
        const float4 hv = *(const float4*)(hcol + k * 132);
        const ulonglong2 wA = *(const ulonglong2*)(wrow + k * 68);
        const ulonglong2 wB = *(const ulonglong2*)(wrow + k * 68 + 4);
        unsigned long long hb;
        hb = pk2(hv.x, hv.x);
        fma2(acc[0],  hb, wA.x); fma2(acc[1],  hb, wA.y);
        fma2(acc[2],  hb, wB.x); fma2(acc[3],  hb, wB.y);
        hb = pk2(hv.y, hv.y);
        fma2(acc[4],  hb, wA.x); fma2(acc[5],  hb, wA.y);
        fma2(acc[6],  hb, wB.x); fma2(acc[7],  hb, wB.y);
        hb = pk2(hv.z, hv.z);
        fma2(acc[8],  hb, wA.x); fma2(acc[9],  hb, wA.y);
        fma2(acc[10], hb, wB.x); fma2(acc[11], hb, wB.y);
        hb = pk2(hv.w, hv.w);
        fma2(acc[12], hb, wA.x); fma2(acc[13], hb, wA.y);
        fma2(acc[14], hb, wB.x); fma2(acc[15], hb, wB.y);
    }

    // ---- coalesced stores: 8 lanes (cg 0..7) cover one 256B batch row ----
    const int gb0 = bid * 128 + w * 16 + bg * 4;
    #pragma unroll
    for (int b = 0; b < 4; b++) {
        float* op = out + (gb0 + b) * 64 + cg * 8;
        float4 v0, v1;
        upk2(acc[b * 4 + 0], v0.x, v0.y); upk2(acc[b * 4 + 1], v0.z, v0.w);
        upk2(acc[b * 4 + 2], v1.x, v1.y); upk2(acc[b * 4 + 3], v1.z, v1.w);
        *(float4*)op = v0;
        *(float4*)(op + 4) = v1;
    }
}

// ============================== launch ======================================
extern "C" void kernel_launch(void* const* d_in, const int* in_sizes, int n_in,
                              void* d_out, int out_size)
{
    const int*   seqs  = (const int*)  d_in[0];
    const int*   qtok  = (const int*)  d_in[1];
    const float* embed = (const float*)d_in[2];
    const float* gw1   = (const float*)d_in[3];
    const float* gb1   = (const float*)d_in[4];
    const float* gw2   = (const float*)d_in[5];
    const float* gb2   = (const float*)d_in[6];
    const float* rw1   = (const float*)d_in[7];
    const float* rb1   = (const float*)d_in[8];
    const float* rw2   = (const float*)d_in[9];
    const float* rb2   = (const float*)d_in[10];

    cudaFuncSetAttribute(main_kernel,
                         cudaFuncAttributeMaxDynamicSharedMemorySize,
                         K2_SMEM_BYTES);

    precompute_kernel<<<129, 128>>>(embed, gw1, gb1, gw2, gb2, rw1, rb1);
    main_kernel<<<256, 256, K2_SMEM_BYTES>>>(seqs, qtok, rw2, rb2, (float*)d_out);
}